// round 12
// baseline (speedup 1.0000x reference)
#include <cuda_runtime.h>

// Controlled 2-qubit gate on a 2^26 fp32 statevector.
// Targets: qubits 0,1 -> bits 25,24 of the flat index. Control: qubit 2 -> bit 23.
// Best config (R11, 74.0us): 1 float4 granule x 4 t-streams per thread,
// warp-uniform control branch, write-through (.wt) stores.
// Single change vs R11: LAST-USE loads (ld.global.lu) — the read stream has
// zero reuse, so lines are dropped right after delivery, freeing L2 tag/sector
// state against the continuous .wt write stream.

#define QGRP (1 << 22)   // float4-granule count per t-stream (2^24 floats / 4)

__device__ __forceinline__ float4 ldlu4(const float4* p) {
    float4 v;
    asm volatile("ld.global.lu.v4.f32 {%0,%1,%2,%3}, [%4];"
                 : "=f"(v.x), "=f"(v.y), "=f"(v.z), "=f"(v.w) : "l"(p));
    return v;
}

__device__ __forceinline__ void stwt4(float4* p, float4 v) {
    asm volatile("st.global.wt.v4.f32 [%0], {%1,%2,%3,%4};"
                 :: "l"(p), "f"(v.x), "f"(v.y), "f"(v.z), "f"(v.w) : "memory");
}

__global__ void __launch_bounds__(256) gate_kernel(
    const float4* __restrict__ in4,
    const float*  __restrict__ m,
    float4*       __restrict__ out4)
{
    const int tid = blockIdx.x * blockDim.x + threadIdx.x;  // 0 .. 2^22-1

    float4 a0 = ldlu4(in4 + tid);
    float4 a1 = ldlu4(in4 + tid + QGRP);
    float4 a2 = ldlu4(in4 + tid + 2 * QGRP);
    float4 a3 = ldlu4(in4 + tid + 3 * QGRP);

    // control bit: bit 23 of element base (= tid*4) -> bit 21 of tid.
    // Uniform across 2^21 consecutive tids -> no warp divergence.
    if ((tid >> 21) & 1) {
        const float m00 = __ldg(m + 0),  m01 = __ldg(m + 1),  m02 = __ldg(m + 2),  m03 = __ldg(m + 3);
        const float m10 = __ldg(m + 4),  m11 = __ldg(m + 5),  m12 = __ldg(m + 6),  m13 = __ldg(m + 7);
        const float m20 = __ldg(m + 8),  m21 = __ldg(m + 9),  m22 = __ldg(m + 10), m23 = __ldg(m + 11);
        const float m30 = __ldg(m + 12), m31 = __ldg(m + 13), m32 = __ldg(m + 14), m33 = __ldg(m + 15);

        float4 y0, y1, y2, y3;
        #define APPLY(c) \
            y0.c = m00 * a0.c + m01 * a1.c + m02 * a2.c + m03 * a3.c; \
            y1.c = m10 * a0.c + m11 * a1.c + m12 * a2.c + m13 * a3.c; \
            y2.c = m20 * a0.c + m21 * a1.c + m22 * a2.c + m23 * a3.c; \
            y3.c = m30 * a0.c + m31 * a1.c + m32 * a2.c + m33 * a3.c;
        APPLY(x); APPLY(y); APPLY(z); APPLY(w);
        #undef APPLY

        a0 = y0; a1 = y1; a2 = y2; a3 = y3;
    }

    stwt4(out4 + tid,            a0);
    stwt4(out4 + tid + QGRP,     a1);
    stwt4(out4 + tid + 2 * QGRP, a2);
    stwt4(out4 + tid + 3 * QGRP, a3);
}

extern "C" void kernel_launch(void* const* d_in, const int* in_sizes, int n_in,
                              void* d_out, int out_size)
{
    const float* x = (const float*)d_in[0];   // 2^26 floats
    const float* m = (const float*)d_in[1];   // 16 floats (4x4 row-major)
    float* out = (float*)d_out;               // 2^26 floats

    const int n_threads = QGRP;               // 2^22 float4 groups
    const int block = 256;
    const int grid = n_threads / block;       // 16384
    gate_kernel<<<grid, block>>>((const float4*)x, m, (float4*)out);
}

// round 13
// speedup vs baseline: 1.0055x; 1.0055x over previous
#include <cuda_runtime.h>

// Controlled 2-qubit gate on a 2^26 fp32 statevector. FINAL (R11 config).
// Targets: qubits 0,1 -> bits 25,24 of the flat index. Control: qubit 2 -> bit 23.
//
// Structure: 1 float4 granule x 4 t-streams per thread (four coalesced streams
// 64MB apart), warp-uniform control branch (bit 21 of granule index, uniform
// over 2^21 consecutive threads), DEFAULT-cache loads, WRITE-THROUGH stores.
//
// Why this is final: traffic is provably minimal (512 MiB: each input byte
// read once, each output byte written once over the poisoned buffer). Eleven
// configurations explored — MLP 4/8, 128/256-bit accesses, block 128/256,
// persistent+prefetch, CE/SM split, and the full load/store cache-op matrix.
// Only .wt stores beat baseline (74.4 -> 74.0us kernel, DRAM-active 82.5%,
// 6.54 TB/s = the GB300 mixed 50/50 read/write HBM3e ceiling). Load-path
// cache demotion (.cs/.lu) consistently regresses; structural changes are
// all neutral or negative.

#define QGRP (1 << 22)   // float4-granule count per t-stream (2^24 floats / 4)

__device__ __forceinline__ void stwt4(float4* p, float4 v) {
    asm volatile("st.global.wt.v4.f32 [%0], {%1,%2,%3,%4};"
                 :: "l"(p), "f"(v.x), "f"(v.y), "f"(v.z), "f"(v.w) : "memory");
}

__global__ void __launch_bounds__(256) gate_kernel(
    const float4* __restrict__ in4,
    const float*  __restrict__ m,
    float4*       __restrict__ out4)
{
    const int tid = blockIdx.x * blockDim.x + threadIdx.x;  // 0 .. 2^22-1

    float4 a0 = in4[tid];
    float4 a1 = in4[tid + QGRP];
    float4 a2 = in4[tid + 2 * QGRP];
    float4 a3 = in4[tid + 3 * QGRP];

    // control bit: bit 23 of element base (= tid*4) -> bit 21 of tid.
    // Uniform across 2^21 consecutive tids -> no warp divergence.
    if ((tid >> 21) & 1) {
        const float m00 = __ldg(m + 0),  m01 = __ldg(m + 1),  m02 = __ldg(m + 2),  m03 = __ldg(m + 3);
        const float m10 = __ldg(m + 4),  m11 = __ldg(m + 5),  m12 = __ldg(m + 6),  m13 = __ldg(m + 7);
        const float m20 = __ldg(m + 8),  m21 = __ldg(m + 9),  m22 = __ldg(m + 10), m23 = __ldg(m + 11);
        const float m30 = __ldg(m + 12), m31 = __ldg(m + 13), m32 = __ldg(m + 14), m33 = __ldg(m + 15);

        float4 y0, y1, y2, y3;
        #define APPLY(c) \
            y0.c = m00 * a0.c + m01 * a1.c + m02 * a2.c + m03 * a3.c; \
            y1.c = m10 * a0.c + m11 * a1.c + m12 * a2.c + m13 * a3.c; \
            y2.c = m20 * a0.c + m21 * a1.c + m22 * a2.c + m23 * a3.c; \
            y3.c = m30 * a0.c + m31 * a1.c + m32 * a2.c + m33 * a3.c;
        APPLY(x); APPLY(y); APPLY(z); APPLY(w);
        #undef APPLY

        a0 = y0; a1 = y1; a2 = y2; a3 = y3;
    }

    stwt4(out4 + tid,            a0);
    stwt4(out4 + tid + QGRP,     a1);
    stwt4(out4 + tid + 2 * QGRP, a2);
    stwt4(out4 + tid + 3 * QGRP, a3);
}

extern "C" void kernel_launch(void* const* d_in, const int* in_sizes, int n_in,
                              void* d_out, int out_size)
{
    const float* x = (const float*)d_in[0];   // 2^26 floats
    const float* m = (const float*)d_in[1];   // 16 floats (4x4 row-major)
    float* out = (float*)d_out;               // 2^26 floats

    const int n_threads = QGRP;               // 2^22 float4 groups
    const int block = 256;
    const int grid = n_threads / block;       // 16384
    gate_kernel<<<grid, block>>>((const float4*)x, m, (float4*)out);
}